// round 13
// baseline (speedup 1.0000x reference)
#include <cuda_runtime.h>
#include <cuda_fp16.h>
#include <math.h>
#include <stdint.h>

#define BATCH 8
#define TLEN  2048
#define DDIM  512
#define BLK   128
#define BLKK  64
#define NTILE (TLEN / BLK)                  // 16
#define NPAIRS (NTILE * (NTILE + 1) / 2)    // 136
#define NTILES (NPAIRS * BATCH)             // 1088
#define NITER (DDIM / BLKK)                 // 8
#define TB    16384                         // operand tile: 128 rows x 128B
#define STAGE_BYTES (2 * TB)                // A, B = 32KB
#define NSTAGE 3
#define GRID_CTAS 296                       // 148 SMs x 2 CTAs
#define SMEM_DYN (NSTAGE * STAGE_BYTES)     // 96KB

__device__ __align__(256) __half g_F[(size_t)BATCH * TLEN * DDIM];

static __device__ __forceinline__ uint32_t smem_u32(const void* p) {
    uint32_t a;
    asm("{ .reg .u64 t; cvta.to.shared.u64 t, %1; cvt.u32.u64 %0, t; }" : "=r"(a) : "l"(p));
    return a;
}

#define CP_ASYNC16(saddr, gptr) \
    asm volatile("cp.async.cg.shared.global [%0], [%1], 16;" :: "r"(saddr), "l"(gptr))
#define CP_COMMIT() asm volatile("cp.async.commit_group;" ::: "memory")
#define CP_WAIT(n)  asm volatile("cp.async.wait_group %0;" :: "n"(n) : "memory")

#define LDSM4(R, addr) \
    asm volatile("ldmatrix.sync.aligned.m8n8.x4.shared.b16 {%0,%1,%2,%3}, [%4];" \
        : "=r"((R)[0]), "=r"((R)[1]), "=r"((R)[2]), "=r"((R)[3]) : "r"(addr))

#define MMA16816(d, a, b0, b1) \
    asm volatile("mma.sync.aligned.m16n8k16.row.col.f32.f16.f16.f32 " \
        "{%0,%1,%2,%3},{%4,%5,%6,%7},{%8,%9},{%0,%1,%2,%3};" \
        : "+f"((d)[0]), "+f"((d)[1]), "+f"((d)[2]), "+f"((d)[3]) \
        : "r"((a)[0]), "r"((a)[1]), "r"((a)[2]), "r"((a)[3]), "r"(b0), "r"(b1))

// ---------------------------------------------------------------------------
// Kernel 1: per-row normalize -> fp16. Warp per row, 8 rows per block.
// ---------------------------------------------------------------------------
__global__ void __launch_bounds__(256) split_kernel(const float* __restrict__ X) {
    const int row  = blockIdx.x * 8 + (threadIdx.x >> 5);
    const int lane = threadIdx.x & 31;
    const float4* xr = (const float4*)(X + (size_t)row * DDIM);

    float4 v[4];
#pragma unroll
    for (int q = 0; q < 4; q++) v[q] = xr[lane + q * 32];

    float s = 0.f;
#pragma unroll
    for (int q = 0; q < 4; q++)
        s += v[q].x * v[q].x + v[q].y * v[q].y + v[q].z * v[q].z + v[q].w * v[q].w;
#pragma unroll
    for (int o = 16; o; o >>= 1) s += __shfl_xor_sync(0xffffffffu, s, o);

    const float rn = 1.0f / fmaxf(sqrtf(s), 1e-12f);

    __half2* Fp = (__half2*)(g_F + (size_t)row * DDIM);
#pragma unroll
    for (int q = 0; q < 4; q++) {
        const int idx = (lane + q * 32) * 2;
        Fp[idx]     = __floats2half2_rn(v[q].x * rn, v[q].y * rn);
        Fp[idx + 1] = __floats2half2_rn(v[q].z * rn, v[q].w * rn);
    }
}

static __device__ __forceinline__ void decode_tile(int t, int& b, int& row0,
                                                   int& col0, bool& diag) {
    b = t / NPAIRS;
    const int lin = t - b * NPAIRS;
    int j = (int)((sqrtf(8.0f * (float)lin + 1.0f) - 1.0f) * 0.5f);
    while ((j + 1) * (j + 2) / 2 <= lin) j++;
    while (j * (j + 1) / 2 > lin) j--;
    const int i = lin - j * (j + 1) / 2;
    row0 = i * BLK; col0 = j * BLK; diag = (i == j);
}

// ---------------------------------------------------------------------------
// Kernel 2: persistent C = F F^T; continuous 3-stage cp.async pipeline
// across tiles; 4 warps of 64x64; 2 CTAs/SM
// ---------------------------------------------------------------------------
__global__ void __launch_bounds__(128, 2) gemm_kernel(float* __restrict__ out) {
    extern __shared__ __align__(1024) char smem[];
    const uint32_t sbase = smem_u32(smem);

    const int tid  = threadIdx.x;
    const int wid  = tid >> 5;
    const int lane = tid & 31;

    const int c  = tid & 7;
    const int r0 = tid >> 3;
    const int wm = (wid >> 1) * 64;
    const int wn = (wid & 1) * 64;
    const int lrow  = lane & 15;
    const int khalf = lane >> 4;

#define ISSUE_P(bb, r00, c00, ch, stg) do {                                    \
        const __half* Fb_ = g_F + (size_t)(bb) * TLEN * DDIM;                  \
        const int kk_ = (ch) * BLKK;                                           \
        const uint32_t st_ = sbase + (uint32_t)(stg) * STAGE_BYTES;            \
        _Pragma("unroll")                                                      \
        for (int q = 0; q < 8; q++) {                                          \
            const int r = r0 + q * 16;                                         \
            const uint32_t so = (uint32_t)(r * 128 + ((c ^ (r & 7)) << 4));    \
            CP_ASYNC16(st_ + so,      Fb_ + (size_t)((r00) + r) * DDIM + kk_ + c * 8); \
            CP_ASYNC16(st_ + TB + so, Fb_ + (size_t)((c00) + r) * DDIM + kk_ + c * 8); \
        }                                                                      \
        CP_COMMIT();                                                           \
    } while (0)

    int t = blockIdx.x;
    int cb, crow, ccol; bool cdiag;
    decode_tile(t, cb, crow, ccol, cdiag);
    int tn = t + GRID_CTAS;
    int nb = 0, nrow = 0, ncol = 0; bool ndiag = false;
    bool has_next = (tn < NTILES);
    if (has_next) decode_tile(tn, nb, nrow, ncol, ndiag);

    // prologue
    ISSUE_P(cb, crow, ccol, 0, 0);
    ISSUE_P(cb, crow, ccol, 1, 1);
    int rs = 0;  // read stage, rotates continuously across tiles

    float acc[4][8][4];

    while (true) {
#pragma unroll
        for (int mf = 0; mf < 4; mf++)
#pragma unroll
            for (int nf = 0; nf < 8; nf++)
#pragma unroll
                for (int u = 0; u < 4; u++) acc[mf][nf][u] = 0.f;

        for (int it = 0; it < NITER; it++) {
            CP_WAIT(1);
            __syncthreads();
            int ws = rs + 2; if (ws >= 3) ws -= 3;
            if (it < 6) {
                ISSUE_P(cb, crow, ccol, it + 2, ws);
            } else if (it == 6) {
                if (has_next) ISSUE_P(nb, nrow, ncol, 0, ws);
                else CP_COMMIT();  // keep group count for final waits
            }
            // it == 7: deferred until after epilogue

            const uint32_t st = sbase + (uint32_t)rs * STAGE_BYTES;
#pragma unroll
            for (int kk2 = 0; kk2 < 4; kk2++) {
                const int chunk0 = kk2 * 2 + khalf;
                uint32_t ah[4][4], bx[4][4];
#pragma unroll
                for (int mf = 0; mf < 4; mf++) {
                    const int row = wm + mf * 16 + lrow;
                    const uint32_t off = row * 128 + ((chunk0 ^ (row & 7)) << 4);
                    LDSM4(ah[mf], st + off);
                }
#pragma unroll
                for (int g = 0; g < 4; g++) {
                    const int row = wn + g * 16 + lrow;
                    const uint32_t off = row * 128 + ((chunk0 ^ (row & 7)) << 4);
                    LDSM4(bx[g], st + TB + off);
                }
#pragma unroll
                for (int mf = 0; mf < 4; mf++)
#pragma unroll
                    for (int nf = 0; nf < 8; nf++) {
                        const int g = nf >> 1, o = nf & 1;
                        MMA16816(acc[mf][nf], ah[mf], bx[g][o], bx[g][o + 2]);
                    }
            }
            rs = rs + 1; if (rs >= 3) rs -= 3;
        }

        // free stages at tile boundary: sA = last-read, sB = one before it;
        // stage (rs)%3 holds the in-flight next-tile chunk 0.
        int sA = rs + 2; if (sA >= 3) sA -= 3;
        int sB = rs + 1; if (sB >= 3) sB -= 3;

        float* outb = out + (size_t)cb * TLEN * TLEN;

        // --- direct tile straight from registers ---
#pragma unroll
        for (int mf = 0; mf < 4; mf++) {
            const int rr = wm + mf * 16 + (lane >> 2);
#pragma unroll
            for (int nf = 0; nf < 8; nf++) {
                const int cc = wn + nf * 8 + (lane & 3) * 2;
                *(float2*)(outb + (size_t)(crow + rr) * TLEN + ccol + cc) =
                    make_float2(acc[mf][nf][0], acc[mf][nf][1]);
                *(float2*)(outb + (size_t)(crow + rr + 8) * TLEN + ccol + cc) =
                    make_float2(acc[mf][nf][2], acc[mf][nf][3]);
            }
        }

        // --- transposed tile via two free 32KB stages, XOR-swizzled ---
        if (!cdiag) {
            __syncthreads();  // all warps done with LDSM reads of sA
            // warp writes columns [wn, wn+64): half sel by wn
            float* hb = (float*)(smem + (size_t)((wn == 0) ? sA : sB) * STAGE_BYTES);
#pragma unroll
            for (int mf = 0; mf < 4; mf++) {
                const int rr = wm + mf * 16 + (lane >> 2);
#pragma unroll
                for (int nf = 0; nf < 8; nf++) {
                    const int cc = wn + nf * 8 + (lane & 3) * 2;
                    const int c0 = cc & 63, c1 = (cc + 1) & 63;
                    const int s0 = (cc & 7) << 2, s1 = ((cc + 1) & 7) << 2;
                    hb[(c0 << 7) + (rr ^ s0)]       = acc[mf][nf][0];
                    hb[(c1 << 7) + (rr ^ s1)]       = acc[mf][nf][1];
                    hb[(c0 << 7) + ((rr + 8) ^ s0)] = acc[mf][nf][2];
                    hb[(c1 << 7) + ((rr + 8) ^ s1)] = acc[mf][nf][3];
                }
            }
            __syncthreads();
#pragma unroll
            for (int tk = 0; tk < 32; tk++) {
                const int tt = wid * 32 + tk;
                const float* rb = (const float*)(smem +
                    (size_t)((tt < 64) ? sA : sB) * STAGE_BYTES);
                const float4 v = *(const float4*)(rb + ((tt & 63) << 7) +
                                                  ((lane * 4) ^ ((tt & 7) << 2)));
                *(float4*)(outb + (size_t)(ccol + tt) * TLEN + crow + lane * 4) = v;
            }
            __syncthreads();  // sB reads done before re-issuing into it
        }

        if (!has_next) break;

        // deferred: next tile chunk 1 into sB (continuous rotation)
        ISSUE_P(nb, nrow, ncol, 1, sB);

        t = tn; cb = nb; crow = nrow; ccol = ncol; cdiag = ndiag;
        tn += GRID_CTAS;
        has_next = (tn < NTILES);
        if (has_next) decode_tile(tn, nb, nrow, ncol, ndiag);
    }
}

extern "C" void kernel_launch(void* const* d_in, const int* in_sizes, int n_in,
                              void* d_out, int out_size) {
    const float* X = (const float*)d_in[0];
    float* out = (float*)d_out;

    split_kernel<<<BATCH * TLEN / 8, 256>>>(X);

    static int cfg_done = 0;
    if (!cfg_done) {
        cudaFuncSetAttribute(gemm_kernel, cudaFuncAttributeMaxDynamicSharedMemorySize, SMEM_DYN);
        cfg_done = 1;
    }
    gemm_kernel<<<GRID_CTAS, 128, SMEM_DYN>>>(out);
}

// round 14
// speedup vs baseline: 1.0788x; 1.0788x over previous
#include <cuda_runtime.h>
#include <cuda_fp16.h>
#include <math.h>
#include <stdint.h>

#define BATCH 8
#define TLEN  2048
#define DDIM  512
#define BLK   128
#define BLKK  64
#define NTILE (TLEN / BLK)                  // 16
#define NPAIRS (NTILE * (NTILE + 1) / 2)    // 136
#define NOFFD (NPAIRS - NTILE)              // 120 strict off-diagonal pairs
#define NITER (DDIM / BLKK)                 // 8
#define TB    16384                         // operand tile: 128 rows x 128B
#define STAGE_BYTES (2 * TB)                // A, B = 32KB
#define NSTAGE 3
#define TPAD 132
#define SMEM_DYN (NSTAGE * STAGE_BYTES)     // 96KB

__device__ __align__(256) __half g_F[(size_t)BATCH * TLEN * DDIM];

static __device__ __forceinline__ uint32_t smem_u32(const void* p) {
    uint32_t a;
    asm("{ .reg .u64 t; cvta.to.shared.u64 t, %1; cvt.u32.u64 %0, t; }" : "=r"(a) : "l"(p));
    return a;
}

#define CP_ASYNC16(saddr, gptr) \
    asm volatile("cp.async.cg.shared.global [%0], [%1], 16;" :: "r"(saddr), "l"(gptr))
#define CP_COMMIT() asm volatile("cp.async.commit_group;" ::: "memory")
#define CP_WAIT(n)  asm volatile("cp.async.wait_group %0;" :: "n"(n) : "memory")

#define LDSM4(R, addr) \
    asm volatile("ldmatrix.sync.aligned.m8n8.x4.shared.b16 {%0,%1,%2,%3}, [%4];" \
        : "=r"((R)[0]), "=r"((R)[1]), "=r"((R)[2]), "=r"((R)[3]) : "r"(addr))

#define MMA16816(d, a, b0, b1) \
    asm volatile("mma.sync.aligned.m16n8k16.row.col.f32.f16.f16.f32 " \
        "{%0,%1,%2,%3},{%4,%5,%6,%7},{%8,%9},{%0,%1,%2,%3};" \
        : "+f"((d)[0]), "+f"((d)[1]), "+f"((d)[2]), "+f"((d)[3]) \
        : "r"((a)[0]), "r"((a)[1]), "r"((a)[2]), "r"((a)[3]), "r"(b0), "r"(b1))

// ---------------------------------------------------------------------------
// Kernel 1: per-row normalize -> fp16. Warp per row, 8 rows per block.
// ---------------------------------------------------------------------------
__global__ void __launch_bounds__(256) split_kernel(const float* __restrict__ X) {
    const int row  = blockIdx.x * 8 + (threadIdx.x >> 5);
    const int lane = threadIdx.x & 31;
    const float4* xr = (const float4*)(X + (size_t)row * DDIM);

    float4 v[4];
#pragma unroll
    for (int q = 0; q < 4; q++) v[q] = xr[lane + q * 32];

    float s = 0.f;
#pragma unroll
    for (int q = 0; q < 4; q++)
        s += v[q].x * v[q].x + v[q].y * v[q].y + v[q].z * v[q].z + v[q].w * v[q].w;
#pragma unroll
    for (int o = 16; o; o >>= 1) s += __shfl_xor_sync(0xffffffffu, s, o);

    const float rn = 1.0f / fmaxf(sqrtf(s), 1e-12f);

    __half2* Fp = (__half2*)(g_F + (size_t)row * DDIM);
#pragma unroll
    for (int q = 0; q < 4; q++) {
        const int idx = (lane + q * 32) * 2;
        Fp[idx]     = __floats2half2_rn(v[q].x * rn, v[q].y * rn);
        Fp[idx + 1] = __floats2half2_rn(v[q].z * rn, v[q].w * rn);
    }
}

// ---------------------------------------------------------------------------
// Kernel 2: C = F F^T, fp16 HMMA
// 4 warps of 64x64; BLKK=64; single-sync 3-stage pipeline; reg-direct epilogue
// off-diagonal tiles first (lin < 120), diagonal tiles last (cheap tail)
// ---------------------------------------------------------------------------
__global__ void __launch_bounds__(128, 2) gemm_kernel(float* __restrict__ out) {
    extern __shared__ __align__(1024) char smem[];
    const uint32_t sbase = smem_u32(smem);

    const int tid  = threadIdx.x;
    const int wid  = tid >> 5;
    const int lane = tid & 31;
    const int b    = blockIdx.y;
    const int lin  = blockIdx.x;

    int i, j;
    if (lin < NOFFD) {
        // strict pairs i < j: lin = j*(j-1)/2 + i
        j = (int)((sqrtf(8.0f * (float)lin + 1.0f) + 1.0f) * 0.5f);
        while (j * (j + 1) / 2 <= lin) j++;
        while (j * (j - 1) / 2 > lin) j--;
        i = lin - j * (j - 1) / 2;
    } else {
        i = j = lin - NOFFD;  // diagonal tiles dispatched last
    }
    const bool diag = (i == j);
    const int row0 = i * BLK;
    const int col0 = j * BLK;

    const __half* Fb = g_F + (size_t)b * TLEN * DDIM;

    const int c  = tid & 7;   // 16B chunk within 128B row
    const int r0 = tid >> 3;  // 0..15
    const uint32_t boffs = diag ? 0u : (uint32_t)TB;  // B reads A tile on diagonal

#define ISSUE(itr) do {                                                        \
        const int kk_ = (itr) * BLKK;                                          \
        const uint32_t st_ = sbase + ((itr) % NSTAGE) * STAGE_BYTES;           \
        _Pragma("unroll")                                                      \
        for (int q = 0; q < 8; q++) {                                          \
            const int r = r0 + q * 16;                                         \
            const uint32_t so = (uint32_t)(r * 128 + ((c ^ (r & 7)) << 4));    \
            CP_ASYNC16(st_ + so, Fb + (size_t)(row0 + r) * DDIM + kk_ + c * 8); \
            if (!diag)                                                         \
                CP_ASYNC16(st_ + TB + so, Fb + (size_t)(col0 + r) * DDIM + kk_ + c * 8); \
        }                                                                      \
        CP_COMMIT();                                                           \
    } while (0)

    ISSUE(0); ISSUE(1);

    // warp grid: 2(m) x 2(n); warp tile 64(m) x 64(n)
    const int wm = (wid >> 1) * 64;
    const int wn = (wid & 1) * 64;
    const int lrow  = lane & 15;
    const int khalf = lane >> 4;

    float acc[4][8][4];
#pragma unroll
    for (int mf = 0; mf < 4; mf++)
#pragma unroll
        for (int nf = 0; nf < 8; nf++)
#pragma unroll
            for (int u = 0; u < 4; u++) acc[mf][nf][u] = 0.f;

    for (int it = 0; it < NITER; it++) {
        CP_WAIT(1);
        __syncthreads();
        if (it + 2 < NITER) ISSUE(it + 2);

        const uint32_t st = sbase + (it % NSTAGE) * STAGE_BYTES;
#pragma unroll
        for (int kk2 = 0; kk2 < 4; kk2++) {
            const int chunk0 = kk2 * 2 + khalf;
            uint32_t ah[4][4], bx[4][4];
#pragma unroll
            for (int mf = 0; mf < 4; mf++) {
                const int row = wm + mf * 16 + lrow;
                const uint32_t off = row * 128 + ((chunk0 ^ (row & 7)) << 4);
                LDSM4(ah[mf], st + off);
            }
#pragma unroll
            for (int g = 0; g < 4; g++) {
                const int row = wn + g * 16 + lrow;
                const uint32_t off = row * 128 + ((chunk0 ^ (row & 7)) << 4);
                LDSM4(bx[g], st + boffs + off);
            }
#pragma unroll
            for (int mf = 0; mf < 4; mf++)
#pragma unroll
                for (int nf = 0; nf < 8; nf++) {
                    const int g = nf >> 1, o = nf & 1;
                    MMA16816(acc[mf][nf], ah[mf], bx[g][o], bx[g][o + 2]);
                }
        }
    }

    float* outb = out + (size_t)b * TLEN * TLEN;

    // --- direct tile straight from registers ---
#pragma unroll
    for (int mf = 0; mf < 4; mf++) {
        const int rr = wm + mf * 16 + (lane >> 2);
#pragma unroll
        for (int nf = 0; nf < 8; nf++) {
            const int cc = wn + nf * 8 + (lane & 3) * 2;
            *(float2*)(outb + (size_t)(row0 + rr) * TLEN + col0 + cc) =
                make_float2(acc[mf][nf][0], acc[mf][nf][1]);
            *(float2*)(outb + (size_t)(row0 + rr + 8) * TLEN + col0 + cc) =
                make_float2(acc[mf][nf][2], acc[mf][nf][3]);
        }
    }

    // --- transposed tile via transposed staging (conflict-free both ways) ---
    if (!diag) {
        float* Ct = (float*)smem;  // [128][TPAD], Ct[col][row]
        __syncthreads();
#pragma unroll
        for (int mf = 0; mf < 4; mf++) {
            const int rr = wm + mf * 16 + (lane >> 2);
#pragma unroll
            for (int nf = 0; nf < 8; nf++) {
                const int cc = wn + nf * 8 + (lane & 3) * 2;
                Ct[cc * TPAD + rr]           = acc[mf][nf][0];
                Ct[(cc + 1) * TPAD + rr]     = acc[mf][nf][1];
                Ct[cc * TPAD + rr + 8]       = acc[mf][nf][2];
                Ct[(cc + 1) * TPAD + rr + 8] = acc[mf][nf][3];
            }
        }
        __syncthreads();
#pragma unroll
        for (int tk = 0; tk < 32; tk++) {
            const int t = wid * 32 + tk;
            const float4 v = *(const float4*)(Ct + t * TPAD + lane * 4);
            *(float4*)(outb + (size_t)(col0 + t) * TLEN + row0 + lane * 4) = v;
        }
    }
}

extern "C" void kernel_launch(void* const* d_in, const int* in_sizes, int n_in,
                              void* d_out, int out_size) {
    const float* X = (const float*)d_in[0];
    float* out = (float*)d_out;

    split_kernel<<<BATCH * TLEN / 8, 256>>>(X);

    static int cfg_done = 0;
    if (!cfg_done) {
        cudaFuncSetAttribute(gemm_kernel, cudaFuncAttributeMaxDynamicSharedMemorySize, SMEM_DYN);
        cfg_done = 1;
    }
    dim3 grid(NPAIRS, BATCH);
    gemm_kernel<<<grid, 128, SMEM_DYN>>>(out);
}

// round 15
// speedup vs baseline: 1.1303x; 1.0478x over previous
#include <cuda_runtime.h>
#include <cuda_fp16.h>
#include <math.h>
#include <stdint.h>

#define BATCH 8
#define TLEN  2048
#define DDIM  512
#define BLK   128
#define BLKK  64
#define NTILE (TLEN / BLK)                  // 16
#define NPAIRS (NTILE * (NTILE + 1) / 2)    // 136
#define NOFFD (NPAIRS - NTILE)              // 120 strict off-diagonal pairs
#define NITER (DDIM / BLKK)                 // 8
#define TB    16384                         // operand tile: 128 rows x 128B
#define STAGE_BYTES (2 * TB)                // A, B = 32KB
#define NSTAGE 3
#define TPAD 132
#define SMEM_DYN (NSTAGE * STAGE_BYTES)     // 96KB

__device__ __align__(256) __half g_F[(size_t)BATCH * TLEN * DDIM];

static __device__ __forceinline__ uint32_t smem_u32(const void* p) {
    uint32_t a;
    asm("{ .reg .u64 t; cvta.to.shared.u64 t, %1; cvt.u32.u64 %0, t; }" : "=r"(a) : "l"(p));
    return a;
}

#define CP_ASYNC16(saddr, gptr) \
    asm volatile("cp.async.cg.shared.global [%0], [%1], 16;" :: "r"(saddr), "l"(gptr))
#define CP_COMMIT() asm volatile("cp.async.commit_group;" ::: "memory")
#define CP_WAIT(n)  asm volatile("cp.async.wait_group %0;" :: "n"(n) : "memory")

#define LDSM4(R, addr) \
    asm volatile("ldmatrix.sync.aligned.m8n8.x4.shared.b16 {%0,%1,%2,%3}, [%4];" \
        : "=r"((R)[0]), "=r"((R)[1]), "=r"((R)[2]), "=r"((R)[3]) : "r"(addr))

#define MMA16816(d, a, b0, b1) \
    asm volatile("mma.sync.aligned.m16n8k16.row.col.f32.f16.f16.f32 " \
        "{%0,%1,%2,%3},{%4,%5,%6,%7},{%8,%9},{%0,%1,%2,%3};" \
        : "+f"((d)[0]), "+f"((d)[1]), "+f"((d)[2]), "+f"((d)[3]) \
        : "r"((a)[0]), "r"((a)[1]), "r"((a)[2]), "r"((a)[3]), "r"(b0), "r"(b1))

// ---------------------------------------------------------------------------
// Kernel 1: per-row normalize -> fp16. Warp per row, 8 rows per block.
// ---------------------------------------------------------------------------
__global__ void __launch_bounds__(256) split_kernel(const float* __restrict__ X) {
    const int row  = blockIdx.x * 8 + (threadIdx.x >> 5);
    const int lane = threadIdx.x & 31;
    const float4* xr = (const float4*)(X + (size_t)row * DDIM);

    float4 v[4];
#pragma unroll
    for (int q = 0; q < 4; q++) v[q] = xr[lane + q * 32];

    float s = 0.f;
#pragma unroll
    for (int q = 0; q < 4; q++)
        s += v[q].x * v[q].x + v[q].y * v[q].y + v[q].z * v[q].z + v[q].w * v[q].w;
#pragma unroll
    for (int o = 16; o; o >>= 1) s += __shfl_xor_sync(0xffffffffu, s, o);

    const float rn = 1.0f / fmaxf(sqrtf(s), 1e-12f);

    __half2* Fp = (__half2*)(g_F + (size_t)row * DDIM);
#pragma unroll
    for (int q = 0; q < 4; q++) {
        const int idx = (lane + q * 32) * 2;
        Fp[idx]     = __floats2half2_rn(v[q].x * rn, v[q].y * rn);
        Fp[idx + 1] = __floats2half2_rn(v[q].z * rn, v[q].w * rn);
    }
}

// ---------------------------------------------------------------------------
// Kernel 2: C = F F^T, fp16 HMMA
// 4 warps of 64x64; BLKK=64; fully-unrolled single-sync 3-stage pipeline
// ---------------------------------------------------------------------------
__global__ void __launch_bounds__(128, 2) gemm_kernel(float* __restrict__ out) {
    extern __shared__ __align__(1024) char smem[];
    const uint32_t sbase = smem_u32(smem);

    const int tid  = threadIdx.x;
    const int wid  = tid >> 5;
    const int lane = tid & 31;
    const int b    = blockIdx.y;
    const int lin  = blockIdx.x;

    int i, j;
    if (lin < NOFFD) {
        // strict pairs i < j: lin = j*(j-1)/2 + i
        j = (int)((sqrtf(8.0f * (float)lin + 1.0f) + 1.0f) * 0.5f);
        while (j * (j + 1) / 2 <= lin) j++;
        while (j * (j - 1) / 2 > lin) j--;
        i = lin - j * (j - 1) / 2;
    } else {
        i = j = lin - NOFFD;  // diagonal tiles dispatched last (cheap tail)
    }
    const bool diag = (i == j);
    const int row0 = i * BLK;
    const int col0 = j * BLK;

    const __half* Fb = g_F + (size_t)b * TLEN * DDIM;

    const int c  = tid & 7;   // 16B chunk within 128B row
    const int r0 = tid >> 3;  // 0..15
    const uint32_t boffs = diag ? 0u : (uint32_t)TB;  // B reads A tile on diagonal

#define ISSUE(itr) do {                                                        \
        const int kk_ = (itr) * BLKK;                                          \
        const uint32_t st_ = sbase + ((itr) % NSTAGE) * STAGE_BYTES;           \
        _Pragma("unroll")                                                      \
        for (int q = 0; q < 8; q++) {                                          \
            const int r = r0 + q * 16;                                         \
            const uint32_t so = (uint32_t)(r * 128 + ((c ^ (r & 7)) << 4));    \
            CP_ASYNC16(st_ + so, Fb + (size_t)(row0 + r) * DDIM + kk_ + c * 8); \
            if (!diag)                                                         \
                CP_ASYNC16(st_ + TB + so, Fb + (size_t)(col0 + r) * DDIM + kk_ + c * 8); \
        }                                                                      \
        CP_COMMIT();                                                           \
    } while (0)

    ISSUE(0); ISSUE(1);

    // warp grid: 2(m) x 2(n); warp tile 64(m) x 64(n)
    const int wm = (wid >> 1) * 64;
    const int wn = (wid & 1) * 64;
    const int lrow  = lane & 15;
    const int khalf = lane >> 4;

    float acc[4][8][4];
#pragma unroll
    for (int mf = 0; mf < 4; mf++)
#pragma unroll
        for (int nf = 0; nf < 8; nf++)
#pragma unroll
            for (int u = 0; u < 4; u++) acc[mf][nf][u] = 0.f;

#define KK2BLOCK(st_, kk2v) do {                                               \
        const int chunk0 = (kk2v) * 2 + khalf;                                 \
        uint32_t ah[4][4], bx[4][4];                                           \
        _Pragma("unroll")                                                      \
        for (int mf = 0; mf < 4; mf++) {                                       \
            const int row = wm + mf * 16 + lrow;                               \
            const uint32_t off = row * 128 + ((chunk0 ^ (row & 7)) << 4);      \
            LDSM4(ah[mf], (st_) + off);                                        \
        }                                                                      \
        _Pragma("unroll")                                                      \
        for (int g = 0; g < 4; g++) {                                          \
            const int row = wn + g * 16 + lrow;                                \
            const uint32_t off = row * 128 + ((chunk0 ^ (row & 7)) << 4);      \
            LDSM4(bx[g], (st_) + boffs + off);                                 \
        }                                                                      \
        _Pragma("unroll")                                                      \
        for (int mf = 0; mf < 4; mf++)                                         \
            _Pragma("unroll")                                                  \
            for (int nf = 0; nf < 8; nf++) {                                   \
                const int g = nf >> 1, o = nf & 1;                             \
                MMA16816(acc[mf][nf], ah[mf], bx[g][o], bx[g][o + 2]);         \
            }                                                                  \
    } while (0)

#pragma unroll
    for (int it = 0; it < NITER; it++) {
        if (it == NITER - 1) { CP_WAIT(0); }  // last stage: all groups done
        else                 { CP_WAIT(1); }
        __syncthreads();

        const uint32_t st = sbase + (it % NSTAGE) * STAGE_BYTES;
        // first MMA block before issuing next prefetch: barrier->MMA fast path
        KK2BLOCK(st, 0);
        if (it + 2 < NITER) ISSUE(it + 2);
        KK2BLOCK(st, 1);
        KK2BLOCK(st, 2);
        KK2BLOCK(st, 3);
    }

    float* outb = out + (size_t)b * TLEN * TLEN;

    // --- direct tile straight from registers ---
#pragma unroll
    for (int mf = 0; mf < 4; mf++) {
        const int rr = wm + mf * 16 + (lane >> 2);
#pragma unroll
        for (int nf = 0; nf < 8; nf++) {
            const int cc = wn + nf * 8 + (lane & 3) * 2;
            *(float2*)(outb + (size_t)(row0 + rr) * TLEN + col0 + cc) =
                make_float2(acc[mf][nf][0], acc[mf][nf][1]);
            *(float2*)(outb + (size_t)(row0 + rr + 8) * TLEN + col0 + cc) =
                make_float2(acc[mf][nf][2], acc[mf][nf][3]);
        }
    }

    // --- transposed tile via transposed staging (conflict-free both ways) ---
    if (!diag) {
        float* Ct = (float*)smem;  // [128][TPAD], Ct[col][row]
        __syncthreads();
#pragma unroll
        for (int mf = 0; mf < 4; mf++) {
            const int rr = wm + mf * 16 + (lane >> 2);
#pragma unroll
            for (int nf = 0; nf < 8; nf++) {
                const int cc = wn + nf * 8 + (lane & 3) * 2;
                Ct[cc * TPAD + rr]           = acc[mf][nf][0];
                Ct[(cc + 1) * TPAD + rr]     = acc[mf][nf][1];
                Ct[cc * TPAD + rr + 8]       = acc[mf][nf][2];
                Ct[(cc + 1) * TPAD + rr + 8] = acc[mf][nf][3];
            }
        }
        __syncthreads();
#pragma unroll
        for (int tk = 0; tk < 32; tk++) {
            const int t = wid * 32 + tk;
            const float4 v = *(const float4*)(Ct + t * TPAD + lane * 4);
            *(float4*)(outb + (size_t)(col0 + t) * TLEN + row0 + lane * 4) = v;
        }
    }
}

extern "C" void kernel_launch(void* const* d_in, const int* in_sizes, int n_in,
                              void* d_out, int out_size) {
    const float* X = (const float*)d_in[0];
    float* out = (float*)d_out;

    split_kernel<<<BATCH * TLEN / 8, 256>>>(X);

    static int cfg_done = 0;
    if (!cfg_done) {
        cudaFuncSetAttribute(gemm_kernel, cudaFuncAttributeMaxDynamicSharedMemorySize, SMEM_DYN);
        cfg_done = 1;
    }
    dim3 grid(NPAIRS, BATCH);
    gemm_kernel<<<grid, 128, SMEM_DYN>>>(out);
}

// round 16
// speedup vs baseline: 1.1568x; 1.0234x over previous
#include <cuda_runtime.h>
#include <cuda_fp16.h>
#include <math.h>
#include <stdint.h>

#define BATCH 8
#define TLEN  2048
#define DDIM  512
#define BLK   128
#define BLKK  64
#define NTILE (TLEN / BLK)                  // 16
#define NPAIRS (NTILE * (NTILE + 1) / 2)    // 136
#define NOFFD (NPAIRS - NTILE)              // 120 strict off-diagonal pairs
#define NITER (DDIM / BLKK)                 // 8
#define TB    16384                         // operand tile: 128 rows x 128B
#define STAGE_BYTES (2 * TB)                // A, B = 32KB
#define NSTAGE 3
#define SMEM_DYN (NSTAGE * STAGE_BYTES)     // 96KB

__device__ __align__(256) __half g_F[(size_t)BATCH * TLEN * DDIM];

static __device__ __forceinline__ uint32_t smem_u32(const void* p) {
    uint32_t a;
    asm("{ .reg .u64 t; cvta.to.shared.u64 t, %1; cvt.u32.u64 %0, t; }" : "=r"(a) : "l"(p));
    return a;
}

#define CP_ASYNC16(saddr, gptr) \
    asm volatile("cp.async.cg.shared.global [%0], [%1], 16;" :: "r"(saddr), "l"(gptr))
#define CP_COMMIT() asm volatile("cp.async.commit_group;" ::: "memory")
#define CP_WAIT(n)  asm volatile("cp.async.wait_group %0;" :: "n"(n) : "memory")

#define LDSM4(R, addr) \
    asm volatile("ldmatrix.sync.aligned.m8n8.x4.shared.b16 {%0,%1,%2,%3}, [%4];" \
        : "=r"((R)[0]), "=r"((R)[1]), "=r"((R)[2]), "=r"((R)[3]) : "r"(addr))

#define MMA16816(d, a, b0, b1) \
    asm volatile("mma.sync.aligned.m16n8k16.row.col.f32.f16.f16.f32 " \
        "{%0,%1,%2,%3},{%4,%5,%6,%7},{%8,%9},{%0,%1,%2,%3};" \
        : "+f"((d)[0]), "+f"((d)[1]), "+f"((d)[2]), "+f"((d)[3]) \
        : "r"((a)[0]), "r"((a)[1]), "r"((a)[2]), "r"((a)[3]), "r"(b0), "r"(b1))

// ---------------------------------------------------------------------------
// Kernel 1: per-row normalize -> fp16. Warp per row, 8 rows per block.
// ---------------------------------------------------------------------------
__global__ void __launch_bounds__(256) split_kernel(const float* __restrict__ X) {
    const int row  = blockIdx.x * 8 + (threadIdx.x >> 5);
    const int lane = threadIdx.x & 31;
    const float4* xr = (const float4*)(X + (size_t)row * DDIM);

    float4 v[4];
#pragma unroll
    for (int q = 0; q < 4; q++) v[q] = xr[lane + q * 32];

    float s = 0.f;
#pragma unroll
    for (int q = 0; q < 4; q++)
        s += v[q].x * v[q].x + v[q].y * v[q].y + v[q].z * v[q].z + v[q].w * v[q].w;
#pragma unroll
    for (int o = 16; o; o >>= 1) s += __shfl_xor_sync(0xffffffffu, s, o);

    const float rn = 1.0f / fmaxf(sqrtf(s), 1e-12f);

    __half2* Fp = (__half2*)(g_F + (size_t)row * DDIM);
#pragma unroll
    for (int q = 0; q < 4; q++) {
        const int idx = (lane + q * 32) * 2;
        Fp[idx]     = __floats2half2_rn(v[q].x * rn, v[q].y * rn);
        Fp[idx + 1] = __floats2half2_rn(v[q].z * rn, v[q].w * rn);
    }
}

// ---------------------------------------------------------------------------
// Kernel 2: C = F F^T, fp16 HMMA
// 4 warps of 64x64; BLKK=64; fully-unrolled single-sync 3-stage pipeline;
// register-direct epilogue for BOTH tiles (no staging, no post-loop barriers)
// ---------------------------------------------------------------------------
__global__ void __launch_bounds__(128, 2) gemm_kernel(float* __restrict__ out) {
    extern __shared__ __align__(1024) char smem[];
    const uint32_t sbase = smem_u32(smem);

    const int tid  = threadIdx.x;
    const int wid  = tid >> 5;
    const int lane = tid & 31;
    const int b    = blockIdx.y;
    const int lin  = blockIdx.x;

    int i, j;
    if (lin < NOFFD) {
        // strict pairs i < j: lin = j*(j-1)/2 + i
        j = (int)((sqrtf(8.0f * (float)lin + 1.0f) + 1.0f) * 0.5f);
        while (j * (j + 1) / 2 <= lin) j++;
        while (j * (j - 1) / 2 > lin) j--;
        i = lin - j * (j - 1) / 2;
    } else {
        i = j = lin - NOFFD;  // diagonal tiles dispatched last (cheap tail)
    }
    const bool diag = (i == j);
    const int row0 = i * BLK;
    const int col0 = j * BLK;

    const __half* Fb = g_F + (size_t)b * TLEN * DDIM;

    const int c  = tid & 7;   // 16B chunk within 128B row
    const int r0 = tid >> 3;  // 0..15
    const uint32_t boffs = diag ? 0u : (uint32_t)TB;  // B reads A tile on diagonal

// half = 0: rows r0, r0+16..r0+48 ; half = 1: rows r0+64..r0+112
#define ISSUE_HALF(itr, half) do {                                             \
        const int kk_ = (itr) * BLKK;                                          \
        const uint32_t st_ = sbase + ((itr) % NSTAGE) * STAGE_BYTES;           \
        _Pragma("unroll")                                                      \
        for (int q = (half) * 4; q < (half) * 4 + 4; q++) {                    \
            const int r = r0 + q * 16;                                         \
            const uint32_t so = (uint32_t)(r * 128 + ((c ^ (r & 7)) << 4));    \
            CP_ASYNC16(st_ + so, Fb + (size_t)(row0 + r) * DDIM + kk_ + c * 8); \
            if (!diag)                                                         \
                CP_ASYNC16(st_ + TB + so, Fb + (size_t)(col0 + r) * DDIM + kk_ + c * 8); \
        }                                                                      \
    } while (0)
#define ISSUE(itr) do { ISSUE_HALF(itr, 0); ISSUE_HALF(itr, 1); CP_COMMIT(); } while (0)

    ISSUE(0); ISSUE(1);

    // warp grid: 2(m) x 2(n); warp tile 64(m) x 64(n)
    const int wm = (wid >> 1) * 64;
    const int wn = (wid & 1) * 64;
    const int lrow  = lane & 15;
    const int khalf = lane >> 4;

    float acc[4][8][4];
#pragma unroll
    for (int mf = 0; mf < 4; mf++)
#pragma unroll
        for (int nf = 0; nf < 8; nf++)
#pragma unroll
            for (int u = 0; u < 4; u++) acc[mf][nf][u] = 0.f;

#define KK2BLOCK(st_, kk2v) do {                                               \
        const int chunk0 = (kk2v) * 2 + khalf;                                 \
        uint32_t ah[4][4], bx[4][4];                                           \
        _Pragma("unroll")                                                      \
        for (int mf = 0; mf < 4; mf++) {                                       \
            const int row = wm + mf * 16 + lrow;                               \
            const uint32_t off = row * 128 + ((chunk0 ^ (row & 7)) << 4);      \
            LDSM4(ah[mf], (st_) + off);                                        \
        }                                                                      \
        _Pragma("unroll")                                                      \
        for (int g = 0; g < 4; g++) {                                          \
            const int row = wn + g * 16 + lrow;                                \
            const uint32_t off = row * 128 + ((chunk0 ^ (row & 7)) << 4);      \
            LDSM4(bx[g], (st_) + boffs + off);                                 \
        }                                                                      \
        _Pragma("unroll")                                                      \
        for (int mf = 0; mf < 4; mf++)                                         \
            _Pragma("unroll")                                                  \
            for (int nf = 0; nf < 8; nf++) {                                   \
                const int g = nf >> 1, o = nf & 1;                             \
                MMA16816(acc[mf][nf], ah[mf], bx[g][o], bx[g][o + 2]);         \
            }                                                                  \
    } while (0)

#pragma unroll
    for (int it = 0; it < NITER; it++) {
        if (it == NITER - 1) { CP_WAIT(0); }  // last stage: all groups done
        else                 { CP_WAIT(1); }
        __syncthreads();

        const uint32_t st = sbase + (it % NSTAGE) * STAGE_BYTES;
        KK2BLOCK(st, 0);
        if (it + 2 < NITER) ISSUE_HALF(it + 2, 0);
        KK2BLOCK(st, 1);
        if (it + 2 < NITER) { ISSUE_HALF(it + 2, 1); CP_COMMIT(); }
        KK2BLOCK(st, 2);
        KK2BLOCK(st, 3);
    }

    float* outb = out + (size_t)b * TLEN * TLEN;

    // --- direct tile straight from registers (coalesced float2) ---
#pragma unroll
    for (int mf = 0; mf < 4; mf++) {
        const int rr = wm + mf * 16 + (lane >> 2);
#pragma unroll
        for (int nf = 0; nf < 8; nf++) {
            const int cc = wn + nf * 8 + (lane & 3) * 2;
            *(float2*)(outb + (size_t)(row0 + rr) * TLEN + col0 + cc) =
                make_float2(acc[mf][nf][0], acc[mf][nf][1]);
            *(float2*)(outb + (size_t)(row0 + rr + 8) * TLEN + col0 + cc) =
                make_float2(acc[mf][nf][2], acc[mf][nf][3]);
        }
    }

    // --- transposed tile straight from registers (full-sector scatter) ---
    // per warp-instruction: 4 distinct rows (cc) x 32B fully-written sectors
    if (!diag) {
#pragma unroll
        for (int mf = 0; mf < 4; mf++) {
            const int rr = wm + mf * 16 + (lane >> 2);
#pragma unroll
            for (int nf = 0; nf < 8; nf++) {
                const int cc = wn + nf * 8 + (lane & 3) * 2;
                float* t0 = outb + (size_t)(col0 + cc) * TLEN + row0;
                float* t1 = outb + (size_t)(col0 + cc + 1) * TLEN + row0;
                t0[rr]     = acc[mf][nf][0];
                t1[rr]     = acc[mf][nf][1];
                t0[rr + 8] = acc[mf][nf][2];
                t1[rr + 8] = acc[mf][nf][3];
            }
        }
    }
}

extern "C" void kernel_launch(void* const* d_in, const int* in_sizes, int n_in,
                              void* d_out, int out_size) {
    const float* X = (const float*)d_in[0];
    float* out = (float*)d_out;

    split_kernel<<<BATCH * TLEN / 8, 256>>>(X);

    static int cfg_done = 0;
    if (!cfg_done) {
        cudaFuncSetAttribute(gemm_kernel, cudaFuncAttributeMaxDynamicSharedMemorySize, SMEM_DYN);
        cfg_done = 1;
    }
    dim3 grid(NPAIRS, BATCH);
    gemm_kernel<<<grid, 128, SMEM_DYN>>>(out);
}

// round 17
// speedup vs baseline: 1.1587x; 1.0017x over previous
#include <cuda_runtime.h>
#include <cuda_fp16.h>
#include <math.h>
#include <stdint.h>

#define BATCH 8
#define TLEN  2048
#define DDIM  512
#define BLK   128
#define BLKK  64
#define NTILE (TLEN / BLK)                  // 16
#define NPAIRS (NTILE * (NTILE + 1) / 2)    // 136
#define NOFFD (NPAIRS - NTILE)              // 120 strict off-diagonal pairs
#define NITER (DDIM / BLKK)                 // 8
#define TB    16384                         // operand tile: 128 rows x 128B
#define STAGE_BYTES (2 * TB)                // A, B = 32KB
#define NSTAGE 3
#define SMEM_DYN (NSTAGE * STAGE_BYTES)     // 96KB

__device__ __align__(256) __half g_F[(size_t)BATCH * TLEN * DDIM];

static __device__ __forceinline__ uint32_t smem_u32(const void* p) {
    uint32_t a;
    asm("{ .reg .u64 t; cvta.to.shared.u64 t, %1; cvt.u32.u64 %0, t; }" : "=r"(a) : "l"(p));
    return a;
}

#define CP_ASYNC16(saddr, gptr) \
    asm volatile("cp.async.cg.shared.global [%0], [%1], 16;" :: "r"(saddr), "l"(gptr))
#define CP_COMMIT() asm volatile("cp.async.commit_group;" ::: "memory")
#define CP_WAIT(n)  asm volatile("cp.async.wait_group %0;" :: "n"(n) : "memory")

#define LDSM4(R, addr) \
    asm volatile("ldmatrix.sync.aligned.m8n8.x4.shared.b16 {%0,%1,%2,%3}, [%4];" \
        : "=r"((R)[0]), "=r"((R)[1]), "=r"((R)[2]), "=r"((R)[3]) : "r"(addr))

#define MMA16816(d, a, b0, b1) \
    asm volatile("mma.sync.aligned.m16n8k16.row.col.f32.f16.f16.f32 " \
        "{%0,%1,%2,%3},{%4,%5,%6,%7},{%8,%9},{%0,%1,%2,%3};" \
        : "+f"((d)[0]), "+f"((d)[1]), "+f"((d)[2]), "+f"((d)[3]) \
        : "r"((a)[0]), "r"((a)[1]), "r"((a)[2]), "r"((a)[3]), "r"(b0), "r"(b1))

// ---------------------------------------------------------------------------
// Kernel 1: per-row normalize -> fp16. Warp per row, 8 rows per block.
// ---------------------------------------------------------------------------
__global__ void __launch_bounds__(256) split_kernel(const float* __restrict__ X) {
    const int row  = blockIdx.x * 8 + (threadIdx.x >> 5);
    const int lane = threadIdx.x & 31;
    const float4* xr = (const float4*)(X + (size_t)row * DDIM);

    float4 v[4];
#pragma unroll
    for (int q = 0; q < 4; q++) v[q] = xr[lane + q * 32];

    float s = 0.f;
#pragma unroll
    for (int q = 0; q < 4; q++)
        s += v[q].x * v[q].x + v[q].y * v[q].y + v[q].z * v[q].z + v[q].w * v[q].w;
#pragma unroll
    for (int o = 16; o; o >>= 1) s += __shfl_xor_sync(0xffffffffu, s, o);

    const float rn = 1.0f / fmaxf(sqrtf(s), 1e-12f);

    __half2* Fp = (__half2*)(g_F + (size_t)row * DDIM);
#pragma unroll
    for (int q = 0; q < 4; q++) {
        const int idx = (lane + q * 32) * 2;
        Fp[idx]     = __floats2half2_rn(v[q].x * rn, v[q].y * rn);
        Fp[idx + 1] = __floats2half2_rn(v[q].z * rn, v[q].w * rn);
    }
}

// ---------------------------------------------------------------------------
// Kernel 2: C = F F^T, fp16 HMMA
// 4 warps of 64x64; BLKK=64; unrolled 3-stage pipeline;
// LDSM/MMA manually interleaved (1 B-LDSM ahead, A one kk2 ahead)
// ---------------------------------------------------------------------------
__global__ void __launch_bounds__(128, 2) gemm_kernel(float* __restrict__ out) {
    extern __shared__ __align__(1024) char smem[];
    const uint32_t sbase = smem_u32(smem);

    const int tid  = threadIdx.x;
    const int wid  = tid >> 5;
    const int lane = tid & 31;
    const int b    = blockIdx.y;
    const int lin  = blockIdx.x;

    int i, j;
    if (lin < NOFFD) {
        j = (int)((sqrtf(8.0f * (float)lin + 1.0f) + 1.0f) * 0.5f);
        while (j * (j + 1) / 2 <= lin) j++;
        while (j * (j - 1) / 2 > lin) j--;
        i = lin - j * (j - 1) / 2;
    } else {
        i = j = lin - NOFFD;  // diagonal tiles last (cheap tail)
    }
    const bool diag = (i == j);
    const int row0 = i * BLK;
    const int col0 = j * BLK;

    const __half* Fb = g_F + (size_t)b * TLEN * DDIM;

    const int c  = tid & 7;
    const int r0 = tid >> 3;
    const uint32_t boffs = diag ? 0u : (uint32_t)TB;

#define ISSUE_HALF(itr, half) do {                                             \
        const int kk_ = (itr) * BLKK;                                          \
        const uint32_t st_ = sbase + ((itr) % NSTAGE) * STAGE_BYTES;           \
        _Pragma("unroll")                                                      \
        for (int q = (half) * 4; q < (half) * 4 + 4; q++) {                    \
            const int r = r0 + q * 16;                                         \
            const uint32_t so = (uint32_t)(r * 128 + ((c ^ (r & 7)) << 4));    \
            CP_ASYNC16(st_ + so, Fb + (size_t)(row0 + r) * DDIM + kk_ + c * 8); \
            if (!diag)                                                         \
                CP_ASYNC16(st_ + TB + so, Fb + (size_t)(col0 + r) * DDIM + kk_ + c * 8); \
        }                                                                      \
    } while (0)
#define ISSUE(itr) do { ISSUE_HALF(itr, 0); ISSUE_HALF(itr, 1); CP_COMMIT(); } while (0)

    ISSUE(0); ISSUE(1);

    const int wm = (wid >> 1) * 64;
    const int wn = (wid & 1) * 64;
    const int lrow  = lane & 15;
    const int khalf = lane >> 4;

    float acc[4][8][4];
#pragma unroll
    for (int mf = 0; mf < 4; mf++)
#pragma unroll
        for (int nf = 0; nf < 8; nf++)
#pragma unroll
            for (int u = 0; u < 4; u++) acc[mf][nf][u] = 0.f;

// load all 4 A fragments for k16-block kk2v into af buffer
#define LDSM_A(dst, st_, kk2v) do {                                            \
        const int chunk0_ = (kk2v) * 2 + khalf;                                \
        _Pragma("unroll")                                                      \
        for (int mf = 0; mf < 4; mf++) {                                       \
            const int row = wm + mf * 16 + lrow;                               \
            const uint32_t off = row * 128 + ((chunk0_ ^ (row & 7)) << 4);     \
            LDSM4((dst)[mf], (st_) + off);                                     \
        }                                                                      \
    } while (0)

// load one B fragment (group g of k16-block kk2v)
#define LDSM_B1(dst, st_, kk2v, g) do {                                        \
        const int chunk0_ = (kk2v) * 2 + khalf;                                \
        const int row = wn + (g) * 16 + lrow;                                  \
        const uint32_t off = row * 128 + ((chunk0_ ^ (row & 7)) << 4);         \
        LDSM4((dst), (st_) + boffs + off);                                     \
    } while (0)

// 8 MMAs of one group: all mf against bfrag (nf = 2g, 2g+1)
#define MMA_G(abuf, bfrag, g) do {                                             \
        _Pragma("unroll")                                                      \
        for (int mf = 0; mf < 4; mf++) {                                       \
            MMA16816(acc[mf][2 * (g)],     (abuf)[mf], (bfrag)[0], (bfrag)[2]); \
            MMA16816(acc[mf][2 * (g) + 1], (abuf)[mf], (bfrag)[1], (bfrag)[3]); \
        }                                                                      \
    } while (0)

    uint32_t af[2][4][4], bf[2][4];

#pragma unroll
    for (int it = 0; it < NITER; it++) {
        if (it == NITER - 1) { CP_WAIT(0); }
        else                 { CP_WAIT(1); }
        __syncthreads();

        const uint32_t st = sbase + (it % NSTAGE) * STAGE_BYTES;

        LDSM_A(af[0], st, 0);
        LDSM_B1(bf[0], st, 0, 0);

#pragma unroll
        for (int kk2 = 0; kk2 < 4; kk2++) {
            const int ab = kk2 & 1;
#pragma unroll
            for (int g = 0; g < 4; g++) {
                const int p = (kk2 * 4 + g) & 1;
                // prefetch next B fragment (interleaves with MMAs below)
                if (!(kk2 == 3 && g == 3)) {
                    const int nk = (g == 3) ? kk2 + 1 : kk2;
                    const int ng = (g == 3) ? 0 : g + 1;
                    LDSM_B1(bf[p ^ 1], st, nk, ng);
                }
                // prefetch next kk2's A fragments mid-block
                if (g == 2 && kk2 < 3) LDSM_A(af[ab ^ 1], st, kk2 + 1);
                MMA_G(af[ab], bf[p], g);
            }
            // spread cp.async issue between kk2 blocks
            if (kk2 == 0 && it + 2 < NITER) ISSUE_HALF(it + 2, 0);
            if (kk2 == 1 && it + 2 < NITER) { ISSUE_HALF(it + 2, 1); CP_COMMIT(); }
        }
    }

    float* outb = out + (size_t)b * TLEN * TLEN;

    // --- direct tile straight from registers (coalesced float2) ---
#pragma unroll
    for (int mf = 0; mf < 4; mf++) {
        const int rr = wm + mf * 16 + (lane >> 2);
#pragma unroll
        for (int nf = 0; nf < 8; nf++) {
            const int cc = wn + nf * 8 + (lane & 3) * 2;
            *(float2*)(outb + (size_t)(row0 + rr) * TLEN + col0 + cc) =
                make_float2(acc[mf][nf][0], acc[mf][nf][1]);
            *(float2*)(outb + (size_t)(row0 + rr + 8) * TLEN + col0 + cc) =
                make_float2(acc[mf][nf][2], acc[mf][nf][3]);
        }
    }

    // --- transposed tile straight from registers (full-sector scatter) ---
    if (!diag) {
#pragma unroll
        for (int mf = 0; mf < 4; mf++) {
            const int rr = wm + mf * 16 + (lane >> 2);
#pragma unroll
            for (int nf = 0; nf < 8; nf++) {
                const int cc = wn + nf * 8 + (lane & 3) * 2;
                float* t0 = outb + (size_t)(col0 + cc) * TLEN + row0;
                float* t1 = outb + (size_t)(col0 + cc + 1) * TLEN + row0;
                t0[rr]     = acc[mf][nf][0];
                t1[rr]     = acc[mf][nf][1];
                t0[rr + 8] = acc[mf][nf][2];
                t1[rr + 8] = acc[mf][nf][3];
            }
        }
    }
}

extern "C" void kernel_launch(void* const* d_in, const int* in_sizes, int n_in,
                              void* d_out, int out_size) {
    const float* X = (const float*)d_in[0];
    float* out = (float*)d_out;

    split_kernel<<<BATCH * TLEN / 8, 256>>>(X);

    static int cfg_done = 0;
    if (!cfg_done) {
        cudaFuncSetAttribute(gemm_kernel, cudaFuncAttributeMaxDynamicSharedMemorySize, SMEM_DYN);
        cfg_done = 1;
    }
    dim3 grid(NPAIRS, BATCH);
    gemm_kernel<<<grid, 128, SMEM_DYN>>>(out);
}